// round 6
// baseline (speedup 1.0000x reference)
#include <cuda_runtime.h>
#include <cstdint>
#include <math.h>

#define T_STEPS 512
#define BATCH   32
#define EMBED   512
#define HID     1024
#define G4      4096

#define NB 128
#define NT 1024
#define HBS 257                  // padded h-chunk row stride (odd -> conflict-free LDS.32)
#define HBUF_FLOATS (32 * HBS)   // 8224 per buffer

#define OFF_HN ((size_t)BATCH * T_STEPS * HID)
#define OFF_CN (OFF_HN + (size_t)BATCH * HID)

typedef unsigned long long u64;

__device__ float g_xproj[(size_t)T_STEPS * G4 * BATCH]; // [t][j][b]
__device__ float g_h[2][BATCH * HID];
__device__ unsigned g_count;
__device__ volatile unsigned g_gen;

__device__ __forceinline__ void ffma2(u64 &d, u64 a, u64 b) {
    asm("fma.rn.f32x2 %0, %1, %2, %0;" : "+l"(d) : "l"(a), "l"(b));
}
__device__ __forceinline__ u64 pk2(float x, float y) {
    u64 r; asm("mov.b64 %0, {%1, %2};" : "=l"(r) : "f"(x), "f"(y)); return r;
}
__device__ __forceinline__ float2 upk(u64 v) {
    float2 r; asm("mov.b64 {%0, %1}, %2;" : "=f"(r.x), "=f"(r.y) : "l"(v)); return r;
}

__device__ __forceinline__ void grid_barrier() {
    __syncthreads();
    if (threadIdx.x == 0) {
        unsigned gen = g_gen;
        __threadfence();
        unsigned prev = atomicAdd(&g_count, 1u);
        if (prev == NB - 1) {
            g_count = 0;
            __threadfence();
            g_gen = gen + 1;
        } else {
            while (g_gen == gen) { __nanosleep(32); }
        }
        __threadfence();
    }
    __syncthreads();
}

// ---------------------------------------------------------------------------
// Kernel 1: x_proj[t][j][b] = sum_e emb[ids[b][t]][e] * Wih[j][e]
// 128x128x8 SGEMM, packed f32x2 accumulators. (unchanged)
// ---------------------------------------------------------------------------
__global__ void __launch_bounds__(256, 2) xproj_gemm(
    const int* __restrict__ ids,
    const float* __restrict__ emb,
    const float* __restrict__ Wih)
{
    __shared__ float As[8][132];
    __shared__ float Bs[8][132];

    const int m0  = blockIdx.y * 128;
    const int n0  = blockIdx.x * 128;
    const int tid = threadIdx.x;

    const int mm = tid >> 1;
    const int qa = tid & 1;
    const int gm = m0 + mm;
    const int tt = gm >> 5;
    const int bb = gm & 31;
    const float* arow = emb + (size_t)ids[bb * T_STEPS + tt] * EMBED;
    const float* brow = Wih + (size_t)(n0 + mm) * EMBED;

    const int tm = tid >> 4;
    const int tn = tid & 15;

    u64 accp[8][4];
#pragma unroll
    for (int i = 0; i < 8; i++)
#pragma unroll
        for (int j = 0; j < 4; j++) accp[i][j] = 0ull;

    for (int k0 = 0; k0 < EMBED; k0 += 8) {
        float4 av = *(const float4*)(arow + k0 + qa * 4);
        float4 bv = *(const float4*)(brow + k0 + qa * 4);
        __syncthreads();
        As[qa * 4 + 0][mm] = av.x; As[qa * 4 + 1][mm] = av.y;
        As[qa * 4 + 2][mm] = av.z; As[qa * 4 + 3][mm] = av.w;
        Bs[qa * 4 + 0][mm] = bv.x; Bs[qa * 4 + 1][mm] = bv.y;
        Bs[qa * 4 + 2][mm] = bv.z; Bs[qa * 4 + 3][mm] = bv.w;
        __syncthreads();

#pragma unroll
        for (int kk = 0; kk < 8; kk++) {
            float4 a0 = *(const float4*)(&As[kk][tm * 8]);
            float4 a1 = *(const float4*)(&As[kk][tm * 8 + 4]);
            const u64* bp = (const u64*)(&Bs[kk][tn * 8]);
            u64 b0 = bp[0], b1 = bp[1], b2 = bp[2], b3 = bp[3];
            u64 ad[8];
            ad[0] = pk2(a0.x, a0.x); ad[1] = pk2(a0.y, a0.y);
            ad[2] = pk2(a0.z, a0.z); ad[3] = pk2(a0.w, a0.w);
            ad[4] = pk2(a1.x, a1.x); ad[5] = pk2(a1.y, a1.y);
            ad[6] = pk2(a1.z, a1.z); ad[7] = pk2(a1.w, a1.w);
#pragma unroll
            for (int i = 0; i < 8; i++) {
                ffma2(accp[i][0], ad[i], b0);
                ffma2(accp[i][1], ad[i], b1);
                ffma2(accp[i][2], ad[i], b2);
                ffma2(accp[i][3], ad[i], b3);
            }
        }
    }

#pragma unroll
    for (int i = 0; i < 8; i++) {
        const int gmi = m0 + tm * 8 + i;
        const int t = gmi >> 5;
        const int b = gmi & 31;
        float* base = g_xproj + (size_t)t * G4 * BATCH + b;
#pragma unroll
        for (int jp = 0; jp < 4; jp++) {
            float2 v = upk(accp[i][jp]);
            const int n = n0 + tn * 8 + jp * 2;
            base[(size_t)n * BATCH]       = v.x;
            base[(size_t)(n + 1) * BATCH] = v.y;
        }
    }
}

// ---------------------------------------------------------------------------
// Kernel 2: persistent LSTM, 1024 threads (32 warps, 8/SMSP).
// W_hh slice (32 rows x 1024) resident in smem. h in 4 chunks of 256 k,
// double-buffered (stride 257). Warp = (rq 0..3, ks 0..7): 8 rows x 32-k
// slice per chunk, acc[8] f32x2 in regs. Staging: warp w stages row w
// (contiguous STS.128, conflict-free). 8-way k-partials overlaid on buffer 0.
// ---------------------------------------------------------------------------
__global__ void __launch_bounds__(NT, 1) lstm_seq(
    const float* __restrict__ h0,
    const float* __restrict__ c0,
    const float* __restrict__ Whh,
    float* __restrict__ out)
{
    extern __shared__ float sm[];
    float* Ws   = sm;              // 32*1024 floats (128KB)
    float* hbuf = sm + 32768;      // 2 * 8224 floats
    float* part = hbuf;            // overlay on buffer 0 (8192 <= 8224)

    const int tid = threadIdx.x;
    const int n0  = blockIdx.x * 8;

    // ---- load W_hh slice into smem (once)
    {
        const int rr = tid >> 5, seg = tid & 31;
        const int grow = (rr >> 3) * HID + n0 + (rr & 7);
        const float4* src = (const float4*)(Whh + (size_t)grow * HID);
        float4* dst = (float4*)(Ws + rr * 1024);
#pragma unroll
        for (int q = 0; q < 8; q++) dst[seg + 32 * q] = src[seg + 32 * q];
    }
    // ---- init h ping-pong buffer 0
    if (tid < 256) {
        const int b = tid >> 3, i = tid & 7;
        g_h[0][b * HID + n0 + i] = h0[b * HID + n0 + i];
    }

    const int wid  = tid >> 5, lane = tid & 31;
    const int rq   = wid >> 3;        // 0..3 : rows rq*8..rq*8+7
    const int ks   = wid & 7;         // 0..7 : k-slice within chunk
    const int sb   = wid;             // staging row = warp id (0..31)
    const int ss   = lane;            // float4 index within row-chunk
    const int fi   = (tid >> 5) & 7, fb = tid & 31;  // finalize role (tid<256)
    const int cidx = fb * HID + n0 + fi;
    float c_reg = (tid < 256) ? c0[cidx] : 0.f;
    float h_reg = 0.f;

    const float* wbase = Ws + (rq * 8) * 1024 + ks * 32;

    grid_barrier();

    for (int t = 0; t < T_STEPS; t++) {
        const float* hread = g_h[t & 1];
        float* hwrite      = g_h[(t & 1) ^ 1];

        u64 acc[8];
#pragma unroll
        for (int j = 0; j < 8; j++) acc[j] = 0ull;

        // preload chunk 0 (L2; bypass L1 for cross-SM coherence)
        float4 s0, s1;
        {
            const float4* gsrc = (const float4*)(hread + sb * HID);
            s0 = __ldcg(gsrc + ss);
            s1 = __ldcg(gsrc + ss + 32);
        }

#pragma unroll 1
        for (int c = 0; c < 4; c++) {
            float* buf = hbuf + (c & 1) * HBUF_FLOATS;
            __syncthreads();   // buffer free
            {
                float4* db = (float4*)(buf + sb * HBS);  // row base (16B aligned: 257*4*sb... sb*1028B)
                // 257*sb not 16B-aligned for odd sb -> use scalar stores
                float* dbs = buf + sb * HBS;
                dbs[ss * 4 + 0]   = s0.x; dbs[ss * 4 + 1]   = s0.y;
                dbs[ss * 4 + 2]   = s0.z; dbs[ss * 4 + 3]   = s0.w;
                dbs[128 + ss * 4 + 0] = s1.x; dbs[128 + ss * 4 + 1] = s1.y;
                dbs[128 + ss * 4 + 2] = s1.z; dbs[128 + ss * 4 + 3] = s1.w;
                (void)db;
            }
            if (c < 3) {
                const float4* gsrc = (const float4*)(hread + sb * HID) + (c + 1) * 64;
                s0 = __ldcg(gsrc + ss);
                s1 = __ldcg(gsrc + ss + 32);
            }
            __syncthreads();   // buffer ready

            const float* hb = buf + lane * HBS + ks * 32;  // conflict-free scalar
            const float* wk = wbase + c * 256;
#pragma unroll
            for (int kq = 0; kq < 8; kq++) {
                const float hv0 = hb[kq * 4 + 0];
                const float hv1 = hb[kq * 4 + 1];
                const float hv2 = hb[kq * 4 + 2];
                const float hv3 = hb[kq * 4 + 3];
                const u64 p01 = pk2(hv0, hv1);
                const u64 p23 = pk2(hv2, hv3);
#pragma unroll
                for (int r = 0; r < 8; r++) {
                    const ulonglong2 w = *(const ulonglong2*)(wk + r * 1024 + kq * 4);
                    ffma2(acc[r], p01, w.x);
                    ffma2(acc[r], p23, w.y);
                }
            }
        }

        // x_proj gate loads (issued here so regs don't live across the loop;
        // DRAM latency overlaps partial writes + sync)
        float xg0 = 0.f, xg1 = 0.f, xg2 = 0.f, xg3 = 0.f;
        if (tid < 256) {
            const float* xpt = g_xproj + (size_t)t * G4 * BATCH + fb;
            xg0 = xpt[(size_t)(0 * HID + n0 + fi) * BATCH];
            xg1 = xpt[(size_t)(1 * HID + n0 + fi) * BATCH];
            xg2 = xpt[(size_t)(2 * HID + n0 + fi) * BATCH];
            xg3 = xpt[(size_t)(3 * HID + n0 + fi) * BATCH];
        }

        // fold pairs, write partials: part[ks][row][b] (overlay on buffer 0;
        // safe: chunk 3 compute reads buffer 1 only, buffer 0 next written
        // after the grid barrier)
#pragma unroll
        for (int r = 0; r < 8; r++) {
            float2 v = upk(acc[r]);
            part[ks * 1024 + (rq * 8 + r) * 32 + lane] = v.x + v.y;
        }
        __syncthreads();

        // gate fusion + state update (thread owns (n0+fi, fb))
        if (tid < 256) {
            float g[4] = {xg0, xg1, xg2, xg3};
#pragma unroll
            for (int gg = 0; gg < 4; gg++) {
                const int row = gg * 8 + fi;
#pragma unroll
                for (int kq = 0; kq < 8; kq++) g[gg] += part[kq * 1024 + row * 32 + fb];
            }
            const float I = 1.f / (1.f + expf(-g[0]));
            const float F = 1.f / (1.f + expf(-g[1]));
            const float G = tanhf(g[2]);
            const float O = 1.f / (1.f + expf(-g[3]));
            c_reg = F * c_reg + I * G;
            h_reg = O * tanhf(c_reg);

            hwrite[cidx] = h_reg;
            out[((size_t)fb * T_STEPS + t) * HID + n0 + fi] = h_reg;
        }

        grid_barrier();
    }

    if (tid < 256) {
        out[OFF_HN + cidx] = h_reg;
        out[OFF_CN + cidx] = c_reg;
    }
}

// ---------------------------------------------------------------------------
extern "C" void kernel_launch(void* const* d_in, const int* in_sizes, int n_in,
                              void* d_out, int out_size)
{
    (void)in_sizes; (void)n_in; (void)out_size;
    const int*   ids = (const int*)  d_in[0];
    const float* h0  = (const float*)d_in[1];
    const float* c0  = (const float*)d_in[2];
    const float* emb = (const float*)d_in[3];
    const float* Wih = (const float*)d_in[4];
    const float* Whh = (const float*)d_in[5];
    float* out = (float*)d_out;

    const int smem_bytes = (32768 + 2 * HBUF_FLOATS) * (int)sizeof(float); // 196,864 B
    cudaFuncSetAttribute(lstm_seq, cudaFuncAttributeMaxDynamicSharedMemorySize, smem_bytes);

    dim3 ggrid(G4 / 128, (BATCH * T_STEPS) / 128);
    xproj_gemm<<<ggrid, 256>>>(ids, emb, Wih);
    lstm_seq<<<NB, NT, smem_bytes>>>(h0, c0, Whh, out);
}